// round 13
// baseline (speedup 1.0000x reference)
#include <cuda_runtime.h>

// ---------------- problem constants ----------------
constexpr int Bn = 64;      // batch
constexpr int Ln = 2048;    // sequence length
constexpr int Hn = 512;     // hidden
constexpr int JS = 16;      // j-slices (hidden split)
constexpr int BSL = 8;      // batch-slices
constexpr int NBLK = JS * BSL;   // 128 blocks
constexpr int JB = Hn / JS;      // 32 hidden cols per block
constexpr int BB = Bn / BSL;     // 8 batches per block
constexpr int NTHR = 512;        // 16 warps
constexpr int NW = 16;
constexpr int KC = Hn / NW;      // 32 k per warp

// Shared layout (floats):
//   Wsh[3][512][32]  : 49152  (gate-major, k-major, j contiguous, conflict-free)
//   union { hs[512][8] : 4096 ; scratch[8][768] : 6144 }
constexpr int WSH_FLOATS = 3 * Hn * JB;          // 49152
constexpr int UNION_FLOATS = 8 * 768;            // 6144
constexpr int SMEM_FLOATS = WSH_FLOATS + UNION_FLOATS;  // 55296
constexpr size_t SMEM_BYTES = (size_t)SMEM_FLOATS * 4;  // 221184 B

// Cross-step residual exchange, transposed layout [k*64 + b].
__device__ float g_res[2][Hn * Bn];
// Per-producer epoch counters (8 increments per step), 128B apart.
__device__ unsigned g_flag[BSL * JS * 32];

__global__ void init_kernel() {
    int i = threadIdx.x;
    if (i < BSL * JS) g_flag[i * 32] = 0u;
}

__device__ __forceinline__ unsigned long long pack2(float v) {
    unsigned long long r;
    unsigned u = __float_as_uint(v);
    asm("mov.b64 %0, {%1, %1};" : "=l"(r) : "r"(u));
    return r;
}
__device__ __forceinline__ void fma2(unsigned long long& d,
                                     unsigned long long a,
                                     unsigned long long b) {
    asm("fma.rn.f32x2 %0, %1, %2, %0;" : "+l"(d) : "l"(a), "l"(b));
}
__device__ __forceinline__ float lo32(unsigned long long v) {
    return __uint_as_float((unsigned)(v & 0xffffffffu));
}
__device__ __forceinline__ float hi32(unsigned long long v) {
    return __uint_as_float((unsigned)(v >> 32));
}
__device__ __forceinline__ unsigned ld_acquire_gpu(const unsigned* p) {
    unsigned v;
    asm volatile("ld.acquire.gpu.b32 %0, [%1];" : "=r"(v) : "l"(p) : "memory");
    return v;
}
__device__ __forceinline__ void red_add_release_gpu(unsigned* p, unsigned v) {
    asm volatile("red.add.release.gpu.u32 [%0], %1;" :: "l"(p), "r"(v) : "memory");
}

#define BAR_SYNC(id, n)   asm volatile("bar.sync %0, %1;"   :: "r"(id), "r"(n) : "memory")
#define BAR_ARRIVE(id, n) asm volatile("bar.arrive %0, %1;" :: "r"(id), "r"(n) : "memory")
// Barrier plan (per step):
//  S1 (__syncthreads): all matvec hs-reads done -> spill may write slots
//  bar 1 (G1 arrive, G0 sync, 512): spill done -> merge may read slots
//  bar 3 (G0 sync, 256):            merge done -> gate may read slots
//  bar 2 (G0 arrive, G1 sync, 512): gate reads done -> G1 may STS hs[2048:4096)
//  bar 4 (G0 sync, 256):            all G0 gate reads done -> G0 may STS hs[0:2048)

extern "C" __global__ void __launch_bounds__(NTHR, 1)
gru_persistent_kernel(const float* __restrict__ x,
                      const float* __restrict__ state,
                      const float* __restrict__ W_ih,
                      const float* __restrict__ W_hh,
                      const float* __restrict__ b_ih,
                      const float* __restrict__ b_hh,
                      const float* __restrict__ A,
                      float* __restrict__ out,
                      int write_final)
{
    extern __shared__ float smem[];
    float* Wsh = smem;                       // 49152 floats
    float* hs = smem + WSH_FLOATS;           // union region (4096 used)
    float* scratch = smem + WSH_FLOATS;      // union region (6144 used)

    const int tid = threadIdx.x;
    const int js = blockIdx.x % JS;
    const int bs = blockIdx.x / JS;
    const int lane = tid & 31;
    const int wrp = tid >> 5;

    // ---- one-time: weights slice into SMEM, layout Wsh[g][k][j] ----
    for (int r = 0; r < 3 * JB; r++) {
        int g = r >> 5, jl = r & 31;
        const float* src = W_hh + (size_t)(g * Hn + js * JB + jl) * Hn;
        for (int k = tid; k < Hn; k += NTHR)
            Wsh[g * (Hn * JB) + k * JB + jl] = src[k];
    }

    // ---- per-thread constants (gate role: warps 0..7, b=wrp, j=lane) ----
    const int bl = wrp;
    const int j = lane;
    const int jg = js * JB + j;
    const int bg = bs * BB + (bl & 7);
    const float w_ir = W_ih[jg];
    const float w_iz = W_ih[Hn + jg];
    const float w_in = W_ih[2 * Hn + jg];
    const float cbr = b_ih[jg] + b_hh[jg];
    const float cbz = b_ih[Hn + jg] + b_hh[Hn + jg];
    const float bin = b_ih[2 * Hn + jg];
    const float bhn = b_hh[2 * Hn + jg];
    const float Av = A[0];
    float st = state[(size_t)bg * Hn + jg];
    float hold = st;                      // residual starts at state
    const float* xp = x + (size_t)bg * Ln;
    float xv_cur = (wrp < 8) ? __ldcg(&xp[0]) : 0.f;

    const int kc = wrp;                   // matvec role: warp = k-chunk of 32
    unsigned* my_flag = g_flag + ((bs * JS + wrp) << 5);   // producer I consume
    unsigned* our_flag = g_flag + ((bs * JS + js) << 5);   // flag I publish

    // ---- initial staging from `state` into hs (all 16 warps, own chunk) ----
    for (int i = lane; i < KC * BB; i += 32) {
        int k_off = i >> 3, b = i & 7;
        hs[(wrp * KC + k_off) * BB + b] =
            state[(size_t)(bs * BB + b) * Hn + wrp * KC + k_off];
    }
    __syncthreads();   // Wsh + initial hs ready

#pragma unroll 1
    for (int t = 0; t < Ln; t++) {
        // ---- matvec partials: warp kc covers k in [kc*32, kc*32+32) ----
        unsigned long long acc[12];
#pragma unroll
        for (int i = 0; i < 12; i++) acc[i] = 0ULL;
        {
            const float* wr0 = Wsh + 0 * (Hn * JB) + kc * KC * JB + j;
            const float* wz0 = Wsh + 1 * (Hn * JB) + kc * KC * JB + j;
            const float* wn0 = Wsh + 2 * (Hn * JB) + kc * KC * JB + j;
            const ulonglong2* hp = (const ulonglong2*)(hs + kc * KC * BB);
#pragma unroll 8
            for (int kk = 0; kk < KC; kk++) {
                unsigned long long wr2 = pack2(wr0[kk * JB]);
                unsigned long long wz2 = pack2(wz0[kk * JB]);
                unsigned long long wn2 = pack2(wn0[kk * JB]);
                ulonglong2 hA = hp[kk * 2];
                ulonglong2 hB = hp[kk * 2 + 1];
                fma2(acc[0], wr2, hA.x); fma2(acc[1], wr2, hA.y);
                fma2(acc[2], wr2, hB.x); fma2(acc[3], wr2, hB.y);
                fma2(acc[4], wz2, hA.x); fma2(acc[5], wz2, hA.y);
                fma2(acc[6], wz2, hB.x); fma2(acc[7], wz2, hB.y);
                fma2(acc[8], wn2, hA.x); fma2(acc[9], wn2, hA.y);
                fma2(acc[10], wn2, hB.x); fma2(acc[11], wn2, hB.y);
            }
        }
        __syncthreads();   // S1: all hs reads done (scratch overlaps hs)

        const unsigned want = 8u * (unsigned)(t + 1);

        if (wrp >= 8) {
            // ---- spill partials to slot wrp-8 ----
            float* sl = scratch + (wrp - 8) * 768;
#pragma unroll
            for (int g = 0; g < 3; g++)
#pragma unroll
                for (int p = 0; p < 4; p++) {
                    unsigned long long v = acc[g * 4 + p];
                    sl[g * 256 + (2 * p) * 32 + j] = lo32(v);
                    sl[g * 256 + (2 * p + 1) * 32 + j] = hi32(v);
                }
            BAR_ARRIVE(1, 512);           // spill done -> G0 merge may go

            // ---- stage t+1 into registers (overlaps G0 merge+gate) ----
            while (ld_acquire_gpu(my_flag) < want) { }
            const float4* src = (const float4*)(g_res[t & 1]);
            float4 v0, v1;
            {
                int l = lane;
                int k = wrp * KC + (l >> 1), bq = l & 1;
                v0 = __ldcg(&src[k * 16 + bs * 2 + bq]);
            }
            {
                int l = lane + 32;
                int k = wrp * KC + (l >> 1), bq = l & 1;
                v1 = __ldcg(&src[k * 16 + bs * 2 + bq]);
            }
            BAR_SYNC(2, 512);             // wait: gate slot-reads done
            {
                float4* dst = (float4*)hs;
                int l = lane;
                int k = wrp * KC + (l >> 1), bq = l & 1;
                dst[k * 2 + bq] = v0;
                l = lane + 32;
                k = wrp * KC + (l >> 1); bq = l & 1;
                dst[k * 2 + bq] = v1;
            }
            __syncwarp();
        } else {
            BAR_SYNC(1, 512);             // wait: spill done
            // ---- merge own partials into slot wrp ----
            float* sl = scratch + wrp * 768;
#pragma unroll
            for (int g = 0; g < 3; g++)
#pragma unroll
                for (int p = 0; p < 4; p++) {
                    unsigned long long v = acc[g * 4 + p];
                    float lo = lo32(v) + sl[g * 256 + (2 * p) * 32 + j];
                    float hi = hi32(v) + sl[g * 256 + (2 * p + 1) * 32 + j];
                    sl[g * 256 + (2 * p) * 32 + j] = lo;
                    sl[g * 256 + (2 * p + 1) * 32 + j] = hi;
                }
            BAR_SYNC(3, 256);             // merge done (G0 only)

            // ---- gate phase (b = wrp, j = lane) ----
            float sr = 0.f, sz = 0.f, sn = 0.f;
#pragma unroll
            for (int c = 0; c < 8; c++) {
                sr += scratch[c * 768 + 0 + bl * 32 + j];
                sz += scratch[c * 768 + 256 + bl * 32 + j];
                sn += scratch[c * 768 + 512 + bl * 32 + j];
            }
            float xv = xv_cur;
            float rr = 1.f / (1.f + __expf(-(sr + xv * w_ir + cbr)));
            float zz = 1.f / (1.f + __expf(-(sz + xv * w_iz + cbz)));
            float nn = tanhf(xv * w_in + bin + rr * (sn + bhn));
            hold = (1.f - zz) * nn + zz * hold;     // new residual
            st = fmaf(Av, hold, st);                // accumulator
            g_res[t & 1][jg * Bn + bg] = hold;      // cross-step publish
            __syncwarp();
            if (lane == 0) {                        // early per-warp release
                __threadfence();
                red_add_release_gpu(our_flag, 1u);
            }
            out[((size_t)bg * Ln + t) * Hn + jg] = st;  // off critical path
            BAR_ARRIVE(2, 512);           // my slot-reads done -> G1 may STS

            // ---- prefetch next x, stage own chunk for t+1 ----
            xv_cur = __ldcg(&xp[(t + 1 < Ln) ? t + 1 : t]);
            while (ld_acquire_gpu(my_flag) < want) { }
            const float4* src = (const float4*)(g_res[t & 1]);
            float4 v0, v1;
            {
                int l = lane;
                int k = wrp * KC + (l >> 1), bq = l & 1;
                v0 = __ldcg(&src[k * 16 + bs * 2 + bq]);
            }
            {
                int l = lane + 32;
                int k = wrp * KC + (l >> 1), bq = l & 1;
                v1 = __ldcg(&src[k * 16 + bs * 2 + bq]);
            }
            BAR_SYNC(4, 256);             // all G0 gate reads done (G0 only)
            {
                float4* dst = (float4*)hs;
                int l = lane;
                int k = wrp * KC + (l >> 1), bq = l & 1;
                dst[k * 2 + bq] = v0;
                l = lane + 32;
                k = wrp * KC + (l >> 1); bq = l & 1;
                dst[k * 2 + bq] = v1;
            }
            __syncwarp();
        }
    }

    if (write_final && wrp < 8)
        out[(size_t)Bn * Ln * Hn + (size_t)bg * Hn + jg] = st;
}

extern "C" void kernel_launch(void* const* d_in, const int* in_sizes, int n_in,
                              void* d_out, int out_size) {
    const float* x     = (const float*)d_in[0];
    const float* state = (const float*)d_in[1];
    const float* W_ih  = (const float*)d_in[2];
    const float* W_hh  = (const float*)d_in[3];
    const float* b_ih  = (const float*)d_in[4];
    const float* b_hh  = (const float*)d_in[5];
    const float* A     = (const float*)d_in[6];
    float* out = (float*)d_out;

    long long need = (long long)Bn * Ln * Hn + (long long)Bn * Hn;
    int write_final = ((long long)out_size >= need) ? 1 : 0;

    cudaFuncSetAttribute(gru_persistent_kernel,
                         cudaFuncAttributeMaxDynamicSharedMemorySize,
                         (int)SMEM_BYTES);

    init_kernel<<<1, 128>>>();
    gru_persistent_kernel<<<NBLK, NTHR, SMEM_BYTES>>>(
        x, state, W_ih, W_hh, b_ih, b_hh, A, out, write_final);
}

// round 14
// speedup vs baseline: 1.4970x; 1.4970x over previous
#include <cuda_runtime.h>

// ---------------- problem constants ----------------
constexpr int Bn = 64;      // batch
constexpr int Ln = 2048;    // sequence length
constexpr int Hn = 512;     // hidden
constexpr int JS = 16;      // j-slices (hidden split)
constexpr int BSL = 8;      // batch-slices
constexpr int NBLK = JS * BSL;   // 128 blocks
constexpr int JB = Hn / JS;      // 32 hidden cols per block
constexpr int BB = Bn / BSL;     // 8 batches per block
constexpr int NTHR = 512;        // 16 warps
constexpr int NW = 16;
constexpr int KC = Hn / NW;      // 32 k per warp

// Shared layout (floats):
//   Wsh[3][512][32]  : 49152  (gate-major, k-major, j contiguous, conflict-free)
//   union { hs[512][8] : 4096 ; scratch[8][768] : 6144 }
//   cnt (publish counter) : 8 floats pad
constexpr int WSH_FLOATS = 3 * Hn * JB;          // 49152
constexpr int UNION_FLOATS = 8 * 768;            // 6144
constexpr int SMEM_FLOATS = WSH_FLOATS + UNION_FLOATS + 8;
constexpr size_t SMEM_BYTES = (size_t)SMEM_FLOATS * 4;  // 221216 B

// Cross-step residual exchange: per-(bs, js-producer) contiguous 1KB blobs,
// blob[jl*8 + b] — exactly the consumer's hs chunk order, so staging is a
// straight coalesced copy (2 x 128B-line groups per warp).
__device__ float g_res[2][BSL * JS * (JB * BB)];
// One flag word per producer block, 128B apart; written ONCE per step.
__device__ unsigned g_flag[BSL * JS * 32];

__global__ void init_kernel() {
    int i = threadIdx.x;
    if (i < BSL * JS) g_flag[i * 32] = 0u;
}

__device__ __forceinline__ unsigned long long pack2(float v) {
    unsigned long long r;
    unsigned u = __float_as_uint(v);
    asm("mov.b64 %0, {%1, %1};" : "=l"(r) : "r"(u));
    return r;
}
__device__ __forceinline__ void fma2(unsigned long long& d,
                                     unsigned long long a,
                                     unsigned long long b) {
    asm("fma.rn.f32x2 %0, %1, %2, %0;" : "+l"(d) : "l"(a), "l"(b));
}
__device__ __forceinline__ float lo32(unsigned long long v) {
    return __uint_as_float((unsigned)(v & 0xffffffffu));
}
__device__ __forceinline__ float hi32(unsigned long long v) {
    return __uint_as_float((unsigned)(v >> 32));
}
__device__ __forceinline__ unsigned ld_acquire_gpu(const unsigned* p) {
    unsigned v;
    asm volatile("ld.acquire.gpu.b32 %0, [%1];" : "=r"(v) : "l"(p) : "memory");
    return v;
}
__device__ __forceinline__ void st_release_gpu(unsigned* p, unsigned v) {
    asm volatile("st.release.gpu.b32 [%0], %1;" :: "l"(p), "r"(v) : "memory");
}
__device__ __forceinline__ unsigned smem_u32(const void* p) {
    unsigned a;
    asm("{ .reg .u64 t; cvta.to.shared.u64 t, %1; cvt.u32.u64 %0, t; }"
        : "=r"(a) : "l"(p));
    return a;
}
// fast activations: ex2.approx + rcp.approx (rel err ~1e-7, saturating-safe)
__device__ __forceinline__ float fast_ex2(float a) {
    float r; asm("ex2.approx.f32 %0, %1;" : "=f"(r) : "f"(a)); return r;
}
__device__ __forceinline__ float fast_rcp(float a) {
    float r; asm("rcp.approx.f32 %0, %1;" : "=f"(r) : "f"(a)); return r;
}
__device__ __forceinline__ float sigmoid_f(float x) {
    // 1/(1+e^-x); x<<0 -> ex2(+inf)=inf -> rcp=0; x>>0 -> 1
    return fast_rcp(1.f + fast_ex2(-1.4426950408889634f * x));
}
__device__ __forceinline__ float tanh_f(float x) {
    // 1 - 2/(1+e^{2x}); saturates correctly at +-1
    float t = fast_ex2(2.8853900817779268f * x);
    return 1.f - 2.f * fast_rcp(1.f + t);
}

extern "C" __global__ void __launch_bounds__(NTHR, 1)
gru_persistent_kernel(const float* __restrict__ x,
                      const float* __restrict__ state,
                      const float* __restrict__ W_ih,
                      const float* __restrict__ W_hh,
                      const float* __restrict__ b_ih,
                      const float* __restrict__ b_hh,
                      const float* __restrict__ A,
                      float* __restrict__ out,
                      int write_final)
{
    extern __shared__ float smem[];
    float* Wsh = smem;                       // 49152 floats
    float* hs = smem + WSH_FLOATS;           // union region (4096 used)
    float* scratch = smem + WSH_FLOATS;      // union region (6144 used)
    unsigned* cnt = (unsigned*)(smem + WSH_FLOATS + UNION_FLOATS);
    const unsigned cnt_sa = smem_u32(cnt);

    const int tid = threadIdx.x;
    const int js = blockIdx.x % JS;
    const int bs = blockIdx.x / JS;
    const int lane = tid & 31;
    const int wrp = tid >> 5;

    if (tid == 0) *cnt = 0u;

    // ---- one-time: weights slice into SMEM, layout Wsh[g][k][j] ----
    for (int r = 0; r < 3 * JB; r++) {
        int g = r >> 5, jl = r & 31;
        const float* src = W_hh + (size_t)(g * Hn + js * JB + jl) * Hn;
        for (int k = tid; k < Hn; k += NTHR)
            Wsh[g * (Hn * JB) + k * JB + jl] = src[k];
    }

    // ---- per-thread constants (gate role: warps 0..7, b=wrp, j=lane) ----
    const int bl = wrp;
    const int j = lane;
    const int jg = js * JB + j;
    const int bg = bs * BB + (bl & 7);
    const float w_ir = W_ih[jg];
    const float w_iz = W_ih[Hn + jg];
    const float w_in = W_ih[2 * Hn + jg];
    const float cbr = b_ih[jg] + b_hh[jg];
    const float cbz = b_ih[Hn + jg] + b_hh[Hn + jg];
    const float bin = b_ih[2 * Hn + jg];
    const float bhn = b_hh[2 * Hn + jg];
    const float Av = A[0];
    float st = state[(size_t)bg * Hn + jg];
    float hold = st;                      // residual starts at state
    const float* xp = x + (size_t)bg * Ln;
    float xv_cur = (wrp < 8) ? __ldcg(&xp[0]) : 0.f;

    const int kc = wrp;                   // matvec role: warp = k-chunk of 32
    unsigned* my_flag = g_flag + ((bs * JS + wrp) << 5);   // producer I consume
    unsigned* our_flag = g_flag + ((bs * JS + js) << 5);   // flag I publish
    // my producer's blob base (float4 units): blob index (bs*JS + wrp), 64 f4
    const int my_blob_f4 = (bs * JS + wrp) * (JB * BB / 4);
    const int our_blob = (bs * JS + js) * (JB * BB);

    __syncthreads();   // Wsh + cnt ready

#pragma unroll 1
    for (int t = 0; t < Ln; t++) {
        // ---- per-warp staging into own hs chunk; no block sync needed ----
        if (t == 0) {
            for (int i = lane; i < KC * BB; i += 32) {
                int k_off = i >> 3, b = i & 7;
                hs[(wrp * KC + k_off) * BB + b] =
                    state[(size_t)(bs * BB + b) * Hn + wrp * KC + k_off];
            }
        } else {
            const unsigned want = (unsigned)t;
            while (ld_acquire_gpu(my_flag) < want) { }
            const float4* src = (const float4*)(g_res[(t - 1) & 1]) + my_blob_f4;
            float4* dst = (float4*)hs + wrp * (KC * BB / 4);
            float4 v0 = __ldcg(&src[lane]);
            float4 v1 = __ldcg(&src[lane + 32]);
            dst[lane] = v0;
            dst[lane + 32] = v1;
        }
        __syncwarp();

        // ---- matvec partials: warp kc covers k in [kc*32, kc*32+32) ----
        unsigned long long acc[12];
#pragma unroll
        for (int i = 0; i < 12; i++) acc[i] = 0ULL;
        {
            const float* wr0 = Wsh + 0 * (Hn * JB) + kc * KC * JB + j;
            const float* wz0 = Wsh + 1 * (Hn * JB) + kc * KC * JB + j;
            const float* wn0 = Wsh + 2 * (Hn * JB) + kc * KC * JB + j;
            const ulonglong2* hp = (const ulonglong2*)(hs + kc * KC * BB);
#pragma unroll 8
            for (int kk = 0; kk < KC; kk++) {
                unsigned long long wr2 = pack2(wr0[kk * JB]);
                unsigned long long wz2 = pack2(wz0[kk * JB]);
                unsigned long long wn2 = pack2(wn0[kk * JB]);
                ulonglong2 hA = hp[kk * 2];        // batches 0,1 | 2,3 (bcast)
                ulonglong2 hB = hp[kk * 2 + 1];    // batches 4,5 | 6,7
                fma2(acc[0], wr2, hA.x); fma2(acc[1], wr2, hA.y);
                fma2(acc[2], wr2, hB.x); fma2(acc[3], wr2, hB.y);
                fma2(acc[4], wz2, hA.x); fma2(acc[5], wz2, hA.y);
                fma2(acc[6], wz2, hB.x); fma2(acc[7], wz2, hB.y);
                fma2(acc[8], wn2, hA.x); fma2(acc[9], wn2, hA.y);
                fma2(acc[10], wn2, hB.x); fma2(acc[11], wn2, hB.y);
            }
        }
        __syncthreads();   // S1: all hs reads done (scratch overlaps hs)

        // ---- reduce round 1: warps 8..15 spill to slot wrp-8 ----
        if (wrp >= 8) {
            float* sl = scratch + (wrp - 8) * 768;
#pragma unroll
            for (int g = 0; g < 3; g++)
#pragma unroll
                for (int p = 0; p < 4; p++) {
                    unsigned long long v = acc[g * 4 + p];
                    sl[g * 256 + (2 * p) * 32 + j] = lo32(v);
                    sl[g * 256 + (2 * p + 1) * 32 + j] = hi32(v);
                }
        }
        __syncthreads();   // S2

        // ---- round 2: warps 0..7 merge slot wrp, write back ----
        if (wrp < 8) {
            float* sl = scratch + wrp * 768;
#pragma unroll
            for (int g = 0; g < 3; g++)
#pragma unroll
                for (int p = 0; p < 4; p++) {
                    unsigned long long v = acc[g * 4 + p];
                    float lo = lo32(v) + sl[g * 256 + (2 * p) * 32 + j];
                    float hi = hi32(v) + sl[g * 256 + (2 * p + 1) * 32 + j];
                    sl[g * 256 + (2 * p) * 32 + j] = lo;
                    sl[g * 256 + (2 * p + 1) * 32 + j] = hi;
                }
        }
        __syncthreads();   // S3

        // ---- gate phase (warps 0..7: b=wrp, j=lane) ----
        if (wrp < 8) {
            float sr = 0.f, sz = 0.f, sn = 0.f;
#pragma unroll
            for (int c = 0; c < 8; c++) {
                sr += scratch[c * 768 + 0 + bl * 32 + j];
                sz += scratch[c * 768 + 256 + bl * 32 + j];
                sn += scratch[c * 768 + 512 + bl * 32 + j];
            }
            float xv = xv_cur;
            float rr = sigmoid_f(sr + xv * w_ir + cbr);
            float zz = sigmoid_f(sz + xv * w_iz + cbz);
            float nn = tanh_f(xv * w_in + bin + rr * (sn + bhn));
            hold = (1.f - zz) * nn + zz * hold;     // new residual

            // ---- publish h ASAP: blob write, SMEM counter, single release ----
            g_res[t & 1][our_blob + j * BB + bl] = hold;
            __syncwarp();
            if (lane == 0) {
                unsigned old;
                asm volatile(
                    "atom.acq_rel.cta.shared::cta.add.u32 %0, [%1], 1;"
                    : "=r"(old) : "r"(cnt_sa) : "memory");
                if (old == 8u * (unsigned)t + 7u)       // last gate warp
                    st_release_gpu(our_flag, (unsigned)(t + 1));
            }

            // ---- off critical path: accumulator, output, x prefetch ----
            st = fmaf(Av, hold, st);
            out[((size_t)bg * Ln + t) * Hn + jg] = st;
            xv_cur = __ldcg(&xp[(t + 1 < Ln) ? t + 1 : t]);
        }

        __syncthreads();   // S4: gate scratch reads done -> next staging may STS
    }

    if (write_final && wrp < 8)
        out[(size_t)Bn * Ln * Hn + (size_t)bg * Hn + jg] = st;
}

extern "C" void kernel_launch(void* const* d_in, const int* in_sizes, int n_in,
                              void* d_out, int out_size) {
    const float* x     = (const float*)d_in[0];
    const float* state = (const float*)d_in[1];
    const float* W_ih  = (const float*)d_in[2];
    const float* W_hh  = (const float*)d_in[3];
    const float* b_ih  = (const float*)d_in[4];
    const float* b_hh  = (const float*)d_in[5];
    const float* A     = (const float*)d_in[6];
    float* out = (float*)d_out;

    long long need = (long long)Bn * Ln * Hn + (long long)Bn * Hn;
    int write_final = ((long long)out_size >= need) ? 1 : 0;

    cudaFuncSetAttribute(gru_persistent_kernel,
                         cudaFuncAttributeMaxDynamicSharedMemorySize,
                         (int)SMEM_BYTES);

    init_kernel<<<1, 128>>>();
    gru_persistent_kernel<<<NBLK, NTHR, SMEM_BYTES>>>(
        x, state, W_ih, W_hh, b_ih, b_hh, A, out, write_final);
}

// round 16
// speedup vs baseline: 1.9913x; 1.3302x over previous
#include <cuda_runtime.h>
#include <cuda_bf16.h>
#include <cstdint>

// ---------------- problem constants ----------------
constexpr int Bn = 64;      // batch
constexpr int Ln = 2048;    // sequence length
constexpr int Hn = 512;     // hidden
constexpr int JS = 16;      // j-slices
constexpr int BSL = 8;      // batch-slices
constexpr int NBLK = JS * BSL;   // 128 blocks
constexpr int JB = Hn / JS;      // 32 hidden cols per block
constexpr int BB = Bn / BSL;     // 8 batches per block
constexpr int NTHR = 512;        // 16 warps

constexpr int MROWS = 3 * JB;    // 96 A rows (3 gates x 32 j)
constexpr int PITCH = 520;       // bf16 elems per row (pad 512+8: bank-stride 4)
constexpr int PITCHB = PITCH * 2;   // 1040 bytes

// ---------------- SMEM byte layout ----------------
constexpr int SM_A_HI = 0;                       // 96*1040 = 99840
constexpr int SM_A_LO = 99840;                   // 99840
constexpr int SM_B_HI = 199680;                  // 8*1040  = 8320
constexpr int SM_B_LO = 208000;                  // 8320
constexpr int SM_SCR  = 216320;                  // 2*96*9*4 = 6912
constexpr int SM_CNT  = 223232;                  // 4
constexpr size_t SMEM_BYTES = 223360;

// Cross-step residual exchange: per-(bs,js) 1KB blobs, layout [b][j] (8x32).
__device__ float g_res[2][BSL * JS * (BB * JB)];
__device__ unsigned g_flag[BSL * JS * 32];

__global__ void init_kernel() {
    int i = threadIdx.x;
    if (i < BSL * JS) g_flag[i * 32] = 0u;
}

// ---------------- helpers ----------------
__device__ __forceinline__ unsigned smem_u32(const void* p) {
    unsigned a;
    asm("{ .reg .u64 t; cvta.to.shared.u64 t, %1; cvt.u32.u64 %0, t; }"
        : "=r"(a) : "l"(p));
    return a;
}
__device__ __forceinline__ unsigned ld_acquire_gpu(const unsigned* p) {
    unsigned v;
    asm volatile("ld.acquire.gpu.b32 %0, [%1];" : "=r"(v) : "l"(p) : "memory");
    return v;
}
__device__ __forceinline__ void st_release_gpu(unsigned* p, unsigned v) {
    asm volatile("st.release.gpu.b32 [%0], %1;" :: "l"(p), "r"(v) : "memory");
}
__device__ __forceinline__ float fast_ex2(float a) {
    float r; asm("ex2.approx.f32 %0, %1;" : "=f"(r) : "f"(a)); return r;
}
__device__ __forceinline__ float fast_rcp(float a) {
    float r; asm("rcp.approx.f32 %0, %1;" : "=f"(r) : "f"(a)); return r;
}
__device__ __forceinline__ float sigmoid_f(float x) {
    return fast_rcp(1.f + fast_ex2(-1.4426950408889634f * x));
}
__device__ __forceinline__ float tanh_f(float x) {
    float t = fast_ex2(2.8853900817779268f * x);
    return 1.f - 2.f * fast_rcp(1.f + t);
}
__device__ __forceinline__ uint32_t pack_bf16_pair(float a, float b) {
    uint32_t r;   // low half = bf16(a), high half = bf16(b)
    asm("cvt.rn.bf16x2.f32 %0, %1, %2;" : "=r"(r) : "f"(b), "f"(a));
    return r;
}
__device__ __forceinline__ void mma_bf16(float& c0, float& c1, float& c2,
                                         float& c3, uint32_t a0, uint32_t a1,
                                         uint32_t a2, uint32_t a3,
                                         uint32_t b0, uint32_t b1) {
    asm volatile(
        "mma.sync.aligned.m16n8k16.row.col.f32.bf16.bf16.f32 "
        "{%0,%1,%2,%3}, {%4,%5,%6,%7}, {%8,%9}, {%0,%1,%2,%3};"
        : "+f"(c0), "+f"(c1), "+f"(c2), "+f"(c3)
        : "r"(a0), "r"(a1), "r"(a2), "r"(a3), "r"(b0), "r"(b1));
}

extern "C" __global__ void __launch_bounds__(NTHR, 1)
gru_persistent_kernel(const float* __restrict__ x,
                      const float* __restrict__ state,
                      const float* __restrict__ W_ih,
                      const float* __restrict__ W_hh,
                      const float* __restrict__ b_ih,
                      const float* __restrict__ b_hh,
                      const float* __restrict__ A,
                      float* __restrict__ out,
                      int write_final)
{
    extern __shared__ __align__(16) char smem[];
    float* scrf = (float*)(smem + SM_SCR);
    unsigned* cnt = (unsigned*)(smem + SM_CNT);
    const unsigned cnt_sa = smem_u32(cnt);

    const int tid = threadIdx.x;
    const int js = blockIdx.x % JS;
    const int bs = blockIdx.x / JS;
    const int lane = tid & 31;
    const int wrp = tid >> 5;

    if (tid == 0) *cnt = 0u;

    // ---- one-time: W slice -> bf16 hi/lo planes, row-major, pitch 520 ----
    for (int idx = tid; idx < MROWS * Hn; idx += NTHR) {
        int m = idx >> 9, k = idx & (Hn - 1);
        int g = m >> 5, jl = m & 31;
        float w = W_hh[(size_t)(g * Hn + js * JB + jl) * Hn + k];
        __nv_bfloat16 hi = __float2bfloat16(w);
        float lo = w - __bfloat162float(hi);
        *(__nv_bfloat16*)(smem + SM_A_HI + m * PITCHB + k * 2) = hi;
        *(__nv_bfloat16*)(smem + SM_A_LO + m * PITCHB + k * 2) =
            __float2bfloat16(lo);
    }

    // ---- gate constants (warps 0..7: b=wrp, j=lane) ----
    const int j = lane;
    const int jg = js * JB + j;
    const int bg = bs * BB + (wrp & 7);
    const float w_ir = W_ih[jg];
    const float w_iz = W_ih[Hn + jg];
    const float w_in = W_ih[2 * Hn + jg];
    const float cbr = b_ih[jg] + b_hh[jg];
    const float cbz = b_ih[Hn + jg] + b_hh[Hn + jg];
    const float bin = b_ih[2 * Hn + jg];
    const float bhn = b_hh[2 * Hn + jg];
    const float Av = A[0];
    float st = state[(size_t)bg * Hn + jg];
    float hold = st;
    const float* xp = x + (size_t)bg * Ln;
    float xv_cur = (wrp < 8) ? __ldcg(&xp[0]) : 0.f;

    unsigned* my_flag = g_flag + ((bs * JS + wrp) << 5);
    unsigned* our_flag = g_flag + ((bs * JS + js) << 5);
    const int my_blob = (bs * JS + wrp) << 8;     // floats
    const int our_blob = (bs * JS + js) << 8;

    // ---- compute-warp constants (warps 0..11: mtile=wrp/2, khalf=wrp&1) ----
    const int mtile = wrp >> 1;
    const int kh = wrp & 1;
    const int qr = lane >> 2, qc = lane & 3;
    // A fragment base: row (mtile*16 + qr), k (kh*256 + qc*2)
    const char* pAhi = smem + SM_A_HI + (mtile * 16 + qr) * PITCHB
                     + (kh * 256 + qc * 2) * 2;
    const char* pAlo = pAhi + (SM_A_LO - SM_A_HI);
    // B fragment base: n (lane/4), k (kh*256 + qc*2)
    const char* pBhi = smem + SM_B_HI + qr * PITCHB + (kh * 256 + qc * 2) * 2;
    const char* pBlo = pBhi + (SM_B_LO - SM_B_HI);

    __syncthreads();   // W planes + cnt ready

#pragma unroll 1
    for (int t = 0; t < Ln; t++) {
        // ---- stage: warp w fetches producer w's h, splits bf16, STS B ----
        {
            float4 v[2];
            if (t == 0) {
#pragma unroll
                for (int it = 0; it < 2; it++) {
                    int li = lane + it * 32;
                    int b = li >> 3, j0 = (li & 7) * 4;
                    v[it] = *(const float4*)&state[(size_t)(bs * BB + b) * Hn
                                                   + wrp * JB + j0];
                }
            } else {
                while (ld_acquire_gpu(my_flag) < (unsigned)t) { }
                const float4* src = (const float4*)(g_res[(t - 1) & 1] + my_blob);
#pragma unroll
                for (int it = 0; it < 2; it++)
                    v[it] = __ldcg(&src[lane + it * 32]);
            }
#pragma unroll
            for (int it = 0; it < 2; it++) {
                int li = lane + it * 32;
                int b = li >> 3, j0 = (li & 7) * 4;
                float4 f = v[it];
                __nv_bfloat16 hx = __float2bfloat16(f.x);
                __nv_bfloat16 hy = __float2bfloat16(f.y);
                __nv_bfloat16 hz = __float2bfloat16(f.z);
                __nv_bfloat16 hw = __float2bfloat16(f.w);
                uint32_t hi01 = ((uint32_t)__bfloat16_as_ushort(hy) << 16)
                              | __bfloat16_as_ushort(hx);
                uint32_t hi23 = ((uint32_t)__bfloat16_as_ushort(hw) << 16)
                              | __bfloat16_as_ushort(hz);
                uint32_t lo01 = pack_bf16_pair(f.x - __bfloat162float(hx),
                                               f.y - __bfloat162float(hy));
                uint32_t lo23 = pack_bf16_pair(f.z - __bfloat162float(hz),
                                               f.w - __bfloat162float(hw));
                int o = b * PITCHB + (wrp * JB + j0) * 2;   // 8B aligned
                *(uint2*)(smem + SM_B_HI + o) = make_uint2(hi01, hi23);
                *(uint2*)(smem + SM_B_LO + o) = make_uint2(lo01, lo23);
            }
        }
        __syncthreads();   // S1: B ready; prior scratch reads done

        // ---- HMMA: warps 0..11, D[mtile] over K-half, 3-term bf16 split ----
        if (wrp < 12) {
            float c0 = 0.f, c1 = 0.f, c2 = 0.f, c3 = 0.f;
#pragma unroll
            for (int kt = 0; kt < 16; kt++) {
                const char* ah = pAhi + kt * 32;
                const char* al = pAlo + kt * 32;
                const char* bh = pBhi + kt * 32;
                const char* bl = pBlo + kt * 32;
                uint32_t ah0 = *(const uint32_t*)(ah);
                uint32_t ah1 = *(const uint32_t*)(ah + 8 * PITCHB);
                uint32_t ah2 = *(const uint32_t*)(ah + 16);
                uint32_t ah3 = *(const uint32_t*)(ah + 8 * PITCHB + 16);
                uint32_t bh0 = *(const uint32_t*)(bh);
                uint32_t bh1 = *(const uint32_t*)(bh + 16);
                uint32_t bl0 = *(const uint32_t*)(bl);
                uint32_t bl1 = *(const uint32_t*)(bl + 16);
                mma_bf16(c0, c1, c2, c3, ah0, ah1, ah2, ah3, bh0, bh1);
                mma_bf16(c0, c1, c2, c3, ah0, ah1, ah2, ah3, bl0, bl1);
                uint32_t al0 = *(const uint32_t*)(al);
                uint32_t al1 = *(const uint32_t*)(al + 8 * PITCHB);
                uint32_t al2 = *(const uint32_t*)(al + 16);
                uint32_t al3 = *(const uint32_t*)(al + 8 * PITCHB + 16);
                mma_bf16(c0, c1, c2, c3, al0, al1, al2, al3, bh0, bh1);
            }
            // store partials: scr[kh][row][n], pitch 9 (conflict-light)
            int r0 = kh * 96 + mtile * 16 + qr;
            scrf[r0 * 9 + qc * 2] = c0;
            scrf[r0 * 9 + qc * 2 + 1] = c1;
            scrf[(r0 + 8) * 9 + qc * 2] = c2;
            scrf[(r0 + 8) * 9 + qc * 2 + 1] = c3;
        }
        __syncthreads();   // S2: partials ready

        // ---- gate phase (warps 0..7: b=wrp, j=lane) ----
        if (wrp < 8) {
            float sr = scrf[(0 * 32 + lane) * 9 + wrp]
                     + scrf[(96 + 0 * 32 + lane) * 9 + wrp];
            float sz = scrf[(1 * 32 + lane) * 9 + wrp]
                     + scrf[(96 + 1 * 32 + lane) * 9 + wrp];
            float sn = scrf[(2 * 32 + lane) * 9 + wrp]
                     + scrf[(96 + 2 * 32 + lane) * 9 + wrp];
            float xv = xv_cur;
            float rr = sigmoid_f(sr + xv * w_ir + cbr);
            float zz = sigmoid_f(sz + xv * w_iz + cbz);
            float nn = tanh_f(xv * w_in + bin + rr * (sn + bhn));
            hold = (1.f - zz) * nn + zz * hold;

            // publish: coalesced 128B row, SMEM acq_rel chain, single release
            g_res[t & 1][our_blob + wrp * 32 + lane] = hold;
            __syncwarp();
            if (lane == 0) {
                unsigned old;
                asm volatile("atom.acq_rel.cta.shared::cta.add.u32 %0, [%1], 1;"
                             : "=r"(old) : "r"(cnt_sa) : "memory");
                if (old == 8u * (unsigned)t + 7u)
                    st_release_gpu(our_flag, (unsigned)(t + 1));
            }

            st = fmaf(Av, hold, st);
            out[((size_t)bg * Ln + t) * Hn + jg] = st;
            xv_cur = __ldcg(&xp[(t + 1 < Ln) ? t + 1 : t]);
        }
        // staging(t+1) overwrites B only after S1(t+1); scratch reads done
        // before compute warps can rewrite (they pass S1(t+1) first).
    }

    if (write_final && wrp < 8)
        out[(size_t)Bn * Ln * Hn + (size_t)bg * Hn + jg] = st;
}

extern "C" void kernel_launch(void* const* d_in, const int* in_sizes, int n_in,
                              void* d_out, int out_size) {
    const float* x     = (const float*)d_in[0];
    const float* state = (const float*)d_in[1];
    const float* W_ih  = (const float*)d_in[2];
    const float* W_hh  = (const float*)d_in[3];
    const float* b_ih  = (const float*)d_in[4];
    const float* b_hh  = (const float*)d_in[5];
    const float* A     = (const float*)d_in[6];
    float* out = (float*)d_out;

    long long need = (long long)Bn * Ln * Hn + (long long)Bn * Hn;
    int write_final = ((long long)out_size >= need) ? 1 : 0;

    cudaFuncSetAttribute(gru_persistent_kernel,
                         cudaFuncAttributeMaxDynamicSharedMemorySize,
                         (int)SMEM_BYTES);

    init_kernel<<<1, 128>>>();
    gru_persistent_kernel<<<NBLK, NTHR, SMEM_BYTES>>>(
        x, state, W_ih, W_hh, b_ih, b_hh, A, out, write_final);
}

// round 17
// speedup vs baseline: 2.2579x; 1.1339x over previous
#include <cuda_runtime.h>
#include <cuda_bf16.h>
#include <cstdint>

// ---------------- problem constants ----------------
constexpr int Bn = 64;      // batch
constexpr int Ln = 2048;    // sequence length
constexpr int Hn = 512;     // hidden
constexpr int JS = 16;      // j-slices
constexpr int BSL = 8;      // batch-slices
constexpr int NBLK = JS * BSL;   // 128 blocks
constexpr int JB = Hn / JS;      // 32 hidden cols per block
constexpr int BB = Bn / BSL;     // 8 batches per block
constexpr int NTHR = 512;        // 16 warps

constexpr int MROWS = 3 * JB;    // 96 A rows (3 gates x 32 j)
constexpr int PITCH = 520;       // bf16 elems per row (pad: bank-stride 4)
constexpr int PITCHB = PITCH * 2;   // 1040 bytes

// ---------------- SMEM byte layout ----------------
constexpr int SM_A_HI = 0;                       // 96*1040 = 99840 (init only)
constexpr int SM_A_LO = 99840;                   // 99840
constexpr int SM_B_HI = 199680;                  // 8*1040  = 8320
constexpr int SM_B_LO = 208000;                  // 8320
constexpr int SM_SCR  = 216320;                  // 2*96*9*4 = 6912
constexpr int SM_CNT  = 223232;                  // 4
constexpr size_t SMEM_BYTES = 223360;

// Cross-step residual exchange: per-(bs,js) 1KB blobs, layout [b][j] (8x32).
__device__ float g_res[2][BSL * JS * (BB * JB)];
__device__ unsigned g_flag[BSL * JS * 32];

__global__ void init_kernel() {
    int i = threadIdx.x;
    if (i < BSL * JS) g_flag[i * 32] = 0u;
}

// ---------------- helpers ----------------
__device__ __forceinline__ unsigned smem_u32(const void* p) {
    unsigned a;
    asm("{ .reg .u64 t; cvta.to.shared.u64 t, %1; cvt.u32.u64 %0, t; }"
        : "=r"(a) : "l"(p));
    return a;
}
__device__ __forceinline__ unsigned ld_acquire_gpu(const unsigned* p) {
    unsigned v;
    asm volatile("ld.acquire.gpu.b32 %0, [%1];" : "=r"(v) : "l"(p) : "memory");
    return v;
}
__device__ __forceinline__ void st_release_gpu(unsigned* p, unsigned v) {
    asm volatile("st.release.gpu.b32 [%0], %1;" :: "l"(p), "r"(v) : "memory");
}
__device__ __forceinline__ float fast_ex2(float a) {
    float r; asm("ex2.approx.f32 %0, %1;" : "=f"(r) : "f"(a)); return r;
}
__device__ __forceinline__ float fast_rcp(float a) {
    float r; asm("rcp.approx.f32 %0, %1;" : "=f"(r) : "f"(a)); return r;
}
__device__ __forceinline__ float sigmoid_f(float x) {
    return fast_rcp(1.f + fast_ex2(-1.4426950408889634f * x));
}
__device__ __forceinline__ float tanh_f(float x) {
    float t = fast_ex2(2.8853900817779268f * x);
    return 1.f - 2.f * fast_rcp(1.f + t);
}
__device__ __forceinline__ uint32_t pack_bf16_pair(float a, float b) {
    uint32_t r;   // low half = bf16(a), high half = bf16(b)
    asm("cvt.rn.bf16x2.f32 %0, %1, %2;" : "=r"(r) : "f"(b), "f"(a));
    return r;
}
__device__ __forceinline__ void mma_bf16(float& c0, float& c1, float& c2,
                                         float& c3, uint32_t a0, uint32_t a1,
                                         uint32_t a2, uint32_t a3,
                                         uint32_t b0, uint32_t b1) {
    asm volatile(
        "mma.sync.aligned.m16n8k16.row.col.f32.bf16.bf16.f32 "
        "{%0,%1,%2,%3}, {%4,%5,%6,%7}, {%8,%9}, {%0,%1,%2,%3};"
        : "+f"(c0), "+f"(c1), "+f"(c2), "+f"(c3)
        : "r"(a0), "r"(a1), "r"(a2), "r"(a3), "r"(b0), "r"(b1));
}

extern "C" __global__ void __launch_bounds__(NTHR, 1)
gru_persistent_kernel(const float* __restrict__ x,
                      const float* __restrict__ state,
                      const float* __restrict__ W_ih,
                      const float* __restrict__ W_hh,
                      const float* __restrict__ b_ih,
                      const float* __restrict__ b_hh,
                      const float* __restrict__ A,
                      float* __restrict__ out,
                      int write_final)
{
    extern __shared__ __align__(16) char smem[];
    float* scrf = (float*)(smem + SM_SCR);
    unsigned* cnt = (unsigned*)(smem + SM_CNT);
    const unsigned cnt_sa = smem_u32(cnt);

    const int tid = threadIdx.x;
    const int js = blockIdx.x % JS;
    const int bs = blockIdx.x / JS;
    const int lane = tid & 31;
    const int wrp = tid >> 5;

    if (tid == 0) *cnt = 0u;

    // ---- one-time: W slice -> bf16 hi/lo planes, row-major, pitch 520 ----
    for (int idx = tid; idx < MROWS * Hn; idx += NTHR) {
        int m = idx >> 9, k = idx & (Hn - 1);
        int g = m >> 5, jl = m & 31;
        float w = W_hh[(size_t)(g * Hn + js * JB + jl) * Hn + k];
        __nv_bfloat16 hi = __float2bfloat16(w);
        float lo = w - __bfloat162float(hi);
        *(__nv_bfloat16*)(smem + SM_A_HI + m * PITCHB + k * 2) = hi;
        *(__nv_bfloat16*)(smem + SM_A_LO + m * PITCHB + k * 2) =
            __float2bfloat16(lo);
    }

    // ---- gate constants (warps 0..7: b=wrp, j=lane) ----
    const int j = lane;
    const int jg = js * JB + j;
    const int bg = bs * BB + (wrp & 7);
    const float w_ir = W_ih[jg];
    const float w_iz = W_ih[Hn + jg];
    const float w_in = W_ih[2 * Hn + jg];
    const float cbr = b_ih[jg] + b_hh[jg];
    const float cbz = b_ih[Hn + jg] + b_hh[Hn + jg];
    const float bin = b_ih[2 * Hn + jg];
    const float bhn = b_hh[2 * Hn + jg];
    const float Av = A[0];
    float st = state[(size_t)bg * Hn + jg];
    float hold = st;
    const float* xp = x + (size_t)bg * Ln;
    float xv_cur = (wrp < 8) ? __ldcg(&xp[0]) : 0.f;

    unsigned* my_flag = g_flag + ((bs * JS + wrp) << 5);
    unsigned* our_flag = g_flag + ((bs * JS + js) << 5);
    const int my_blob = (bs * JS + wrp) << 8;     // floats
    const int our_blob = (bs * JS + js) << 8;

    // ---- compute-warp constants (warps 0..11: mtile=wrp/2, khalf=wrp&1) ----
    const int mtile = wrp >> 1;
    const int kh = wrp & 1;
    const int qr = lane >> 2, qc = lane & 3;
    const char* pAhi = smem + SM_A_HI + (mtile * 16 + qr) * PITCHB
                     + (kh * 256 + qc * 2) * 2;
    const char* pAlo = pAhi + (SM_A_LO - SM_A_HI);
    const char* pBhi = smem + SM_B_HI + qr * PITCHB + (kh * 256 + qc * 2) * 2;
    const char* pBlo = pBhi + (SM_B_LO - SM_B_HI);

    __syncthreads();   // W planes + cnt ready

    // ---- hoist A_hi fragments into registers (static across all steps) ----
    uint32_t Ah0[16], Ah1[16], Ah2[16], Ah3[16];
#pragma unroll
    for (int kt = 0; kt < 16; kt++) {
        const char* ah = pAhi + kt * 32;
        Ah0[kt] = *(const uint32_t*)(ah);
        Ah1[kt] = *(const uint32_t*)(ah + 8 * PITCHB);
        Ah2[kt] = *(const uint32_t*)(ah + 16);
        Ah3[kt] = *(const uint32_t*)(ah + 8 * PITCHB + 16);
    }

#pragma unroll 1
    for (int t = 0; t < Ln; t++) {
        // ---- stage: warp w fetches producer w's h, splits bf16, STS B ----
        {
            float4 v[2];
            if (t == 0) {
#pragma unroll
                for (int it = 0; it < 2; it++) {
                    int li = lane + it * 32;
                    int b = li >> 3, j0 = (li & 7) * 4;
                    v[it] = *(const float4*)&state[(size_t)(bs * BB + b) * Hn
                                                   + wrp * JB + j0];
                }
            } else {
                while (ld_acquire_gpu(my_flag) < (unsigned)t) { }
                const float4* src = (const float4*)(g_res[(t - 1) & 1] + my_blob);
#pragma unroll
                for (int it = 0; it < 2; it++)
                    v[it] = __ldcg(&src[lane + it * 32]);
            }
#pragma unroll
            for (int it = 0; it < 2; it++) {
                int li = lane + it * 32;
                int b = li >> 3, j0 = (li & 7) * 4;
                float4 f = v[it];
                __nv_bfloat16 hx = __float2bfloat16(f.x);
                __nv_bfloat16 hy = __float2bfloat16(f.y);
                __nv_bfloat16 hz = __float2bfloat16(f.z);
                __nv_bfloat16 hw = __float2bfloat16(f.w);
                uint32_t hi01 = ((uint32_t)__bfloat16_as_ushort(hy) << 16)
                              | __bfloat16_as_ushort(hx);
                uint32_t hi23 = ((uint32_t)__bfloat16_as_ushort(hw) << 16)
                              | __bfloat16_as_ushort(hz);
                uint32_t lo01 = pack_bf16_pair(f.x - __bfloat162float(hx),
                                               f.y - __bfloat162float(hy));
                uint32_t lo23 = pack_bf16_pair(f.z - __bfloat162float(hz),
                                               f.w - __bfloat162float(hw));
                int o = b * PITCHB + (wrp * JB + j0) * 2;   // 8B aligned
                *(uint2*)(smem + SM_B_HI + o) = make_uint2(hi01, hi23);
                *(uint2*)(smem + SM_B_LO + o) = make_uint2(lo01, lo23);
            }
        }
        __syncthreads();   // S1: B ready; prior scratch reads done

        // ---- HMMA: A_hi from regs; A_lo + B from SMEM; 3-term split ----
        if (wrp < 12) {
            float c0 = 0.f, c1 = 0.f, c2 = 0.f, c3 = 0.f;
#pragma unroll
            for (int kt = 0; kt < 16; kt++) {
                const char* al = pAlo + kt * 32;
                const char* bh = pBhi + kt * 32;
                const char* bl = pBlo + kt * 32;
                uint32_t bh0 = *(const uint32_t*)(bh);
                uint32_t bh1 = *(const uint32_t*)(bh + 16);
                uint32_t bl0 = *(const uint32_t*)(bl);
                uint32_t bl1 = *(const uint32_t*)(bl + 16);
                mma_bf16(c0, c1, c2, c3, Ah0[kt], Ah1[kt], Ah2[kt], Ah3[kt],
                         bh0, bh1);
                mma_bf16(c0, c1, c2, c3, Ah0[kt], Ah1[kt], Ah2[kt], Ah3[kt],
                         bl0, bl1);
                uint32_t al0 = *(const uint32_t*)(al);
                uint32_t al1 = *(const uint32_t*)(al + 8 * PITCHB);
                uint32_t al2 = *(const uint32_t*)(al + 16);
                uint32_t al3 = *(const uint32_t*)(al + 8 * PITCHB + 16);
                mma_bf16(c0, c1, c2, c3, al0, al1, al2, al3, bh0, bh1);
            }
            int r0 = kh * 96 + mtile * 16 + qr;
            scrf[r0 * 9 + qc * 2] = c0;
            scrf[r0 * 9 + qc * 2 + 1] = c1;
            scrf[(r0 + 8) * 9 + qc * 2] = c2;
            scrf[(r0 + 8) * 9 + qc * 2 + 1] = c3;
        }
        __syncthreads();   // S2: partials ready

        // ---- gate phase (warps 0..7: b=wrp, j=lane) ----
        if (wrp < 8) {
            float sr = scrf[(0 * 32 + lane) * 9 + wrp]
                     + scrf[(96 + 0 * 32 + lane) * 9 + wrp];
            float sz = scrf[(1 * 32 + lane) * 9 + wrp]
                     + scrf[(96 + 1 * 32 + lane) * 9 + wrp];
            float sn = scrf[(2 * 32 + lane) * 9 + wrp]
                     + scrf[(96 + 2 * 32 + lane) * 9 + wrp];
            float xv = xv_cur;
            float rr = sigmoid_f(sr + xv * w_ir + cbr);
            float zz = sigmoid_f(sz + xv * w_iz + cbz);
            float nn = tanh_f(xv * w_in + bin + rr * (sn + bhn));
            hold = (1.f - zz) * nn + zz * hold;

            // publish: coalesced 128B row, SMEM acq_rel chain, single release
            g_res[t & 1][our_blob + wrp * 32 + lane] = hold;
            __syncwarp();
            if (lane == 0) {
                unsigned old;
                asm volatile("atom.acq_rel.cta.shared::cta.add.u32 %0, [%1], 1;"
                             : "=r"(old) : "r"(cnt_sa) : "memory");
                if (old == 8u * (unsigned)t + 7u)
                    st_release_gpu(our_flag, (unsigned)(t + 1));
            }

            st = fmaf(Av, hold, st);
            out[((size_t)bg * Ln + t) * Hn + jg] = st;
            xv_cur = __ldcg(&xp[(t + 1 < Ln) ? t + 1 : t]);
        }
    }

    if (write_final && wrp < 8)
        out[(size_t)Bn * Ln * Hn + (size_t)bg * Hn + jg] = st;
}

extern "C" void kernel_launch(void* const* d_in, const int* in_sizes, int n_in,
                              void* d_out, int out_size) {
    const float* x     = (const float*)d_in[0];
    const float* state = (const float*)d_in[1];
    const float* W_ih  = (const float*)d_in[2];
    const float* W_hh  = (const float*)d_in[3];
    const float* b_ih  = (const float*)d_in[4];
    const float* b_hh  = (const float*)d_in[5];
    const float* A     = (const float*)d_in[6];
    float* out = (float*)d_out;

    long long need = (long long)Bn * Ln * Hn + (long long)Bn * Hn;
    int write_final = ((long long)out_size >= need) ? 1 : 0;

    cudaFuncSetAttribute(gru_persistent_kernel,
                         cudaFuncAttributeMaxDynamicSharedMemorySize,
                         (int)SMEM_BYTES);

    init_kernel<<<1, 128>>>();
    gru_persistent_kernel<<<NBLK, NTHR, SMEM_BYTES>>>(
        x, state, W_ih, W_hh, b_ih, b_hh, A, out, write_final);
}